// round 11
// baseline (speedup 1.0000x reference)
#include <cuda_runtime.h>
#include <cuda_fp16.h>
#include <mma.h>
#include <math.h>
#include <stdint.h>

using namespace nvcuda;

#define Nn  20000
#define Ee  80000
#define Hh  64
#define NFf 32
#define Bb  64
#define HID 128

// ---------------- device scratch (no allocations allowed) ----------------
__device__ float  g_X[Nn * Hh];
__device__ float  g_agg[Nn * Hh];              // zeroed at load; k_gru re-zeroes after use
__device__ __half g_hid[Ee * HID];             // edge MLP hidden (fp16)
__device__ __half g_w2h[HID * Hh * Hh];        // W2 in fp16 (1 MB)
__device__ __half g_we[(size_t)Ee * Hh * Hh];  // 655 MB edge weights (fp16)
__device__ float  g_deg[Nn];
__device__ int    g_cnt[Bb];
__device__ int    g_ptr[Bb + 1];
__device__ float  g_en[Nn];
__device__ float  g_hs[Bb * Hh];
__device__ float  g_cs[Bb * Hh];
__device__ float  g_qstar[Bb * 2 * Hh];

__device__ __forceinline__ float sigf(float x) { return 1.0f / (1.0f + expf(-x)); }

// ---------------- prep: W2 -> fp16 ----------------
__global__ void k_prep(const float* __restrict__ w2) {
    int i4 = (blockIdx.x * 256 + threadIdx.x) * 4;
    float4 v = *(const float4*)&w2[i4];
    *(__half2*)&g_w2h[i4]     = __floats2half2_rn(v.x, v.y);
    *(__half2*)&g_w2h[i4 + 2] = __floats2half2_rn(v.z, v.w);
}

// ---------------- lin0: X = relu(x @ W0 + b0) ----------------
__global__ void k_lin0(const float* __restrict__ x, const float* __restrict__ w,
                       const float* __restrict__ b) {
    __shared__ float xs[NFf];
    int n = blockIdx.x, o = threadIdx.x;           // 64 threads
    if (o < NFf) xs[o] = x[n * NFf + o];
    __syncthreads();
    float acc = b[o];
#pragma unroll
    for (int i = 0; i < NFf; i++) acc = fmaf(xs[i], w[i * Hh + o], acc);
    g_X[n * Hh + o] = fmaxf(acc, 0.0f);
}

// ---------------- edge MLP layer 1 (round-8 form): hid = fp16(relu(ea @ W1 + b1)) ----------------
__global__ void k_mlp1(const float* __restrict__ ea, const float* __restrict__ w,
                       const float* __restrict__ b) {
    __shared__ float es[Hh];
    int e = blockIdx.x, j = threadIdx.x;           // 128 threads
    if (j < Hh) es[j] = ea[e * Hh + j];
    __syncthreads();
    float acc = b[j];
#pragma unroll
    for (int i = 0; i < Hh; i++) acc = fmaf(es[i], w[i * HID + j], acc);
    g_hid[e * HID + j] = __float2half_rn(fmaxf(acc, 0.0f));
}

// ---------------- big GEMM (fp16 HMMA): we = fp16(hid @ W2 + b2) ----------------
// Round-4 tile shape; NEW epilogue: bias preloaded into acc, half-frag direct global store.
#define GBM 64
#define GBN 64
#define GBK 64
#define HSTR 72
__global__ __launch_bounds__(256)
void k_gemm_we(const float* __restrict__ bias) {
    __shared__ __half As[GBM * HSTR];     // 64 x 72 half
    __shared__ __half Bs[GBK * HSTR];     // 64 x 72 half
    __shared__ float  bias_s[16 * 68];    // replicated bias rows

    int bn = blockIdx.x;            // 0..63  (col tile)
    int bm = blockIdx.y;            // 0..1249 (row tile)
    int t  = threadIdx.x;           // 256
    int wid = t >> 5;
    int rt = wid & 3;               // 16-row tile
    int ct = wid >> 2;              // 32-col half

    if (t < Hh) {
        float bv = bias[bn * GBN + t];
#pragma unroll
        for (int r = 0; r < 16; r++) bias_s[r * 68 + t] = bv;
    }
    __syncthreads();

    wmma::fragment<wmma::accumulator, 16, 16, 16, float> c0, c1;
    wmma::load_matrix_sync(c0, &bias_s[ct * 32],      68, wmma::mem_row_major);
    wmma::load_matrix_sync(c1, &bias_s[ct * 32 + 16], 68, wmma::mem_row_major);

    const __half* A = g_hid + (size_t)bm * GBM * HID;
    const __half* Bg = g_w2h + bn * GBN;

    int lr = t >> 3;                // 0..31
    int lc = (t & 7) * 8;           // half-index, 8 halfs = 16B

    for (int kt = 0; kt < HID; kt += GBK) {
        *(float4*)&As[lr * HSTR + lc]        = *(const float4*)&A[lr * HID + kt + lc];
        *(float4*)&As[(lr + 32) * HSTR + lc] = *(const float4*)&A[(lr + 32) * HID + kt + lc];
        *(float4*)&Bs[lr * HSTR + lc]        = *(const float4*)&Bg[(size_t)(kt + lr) * (Hh * Hh) + lc];
        *(float4*)&Bs[(lr + 32) * HSTR + lc] = *(const float4*)&Bg[(size_t)(kt + lr + 32) * (Hh * Hh) + lc];
        __syncthreads();
#pragma unroll
        for (int k16 = 0; k16 < GBK / 16; k16++) {
            wmma::fragment<wmma::matrix_a, 16, 16, 16, __half, wmma::row_major> af;
            wmma::fragment<wmma::matrix_b, 16, 16, 16, __half, wmma::row_major> bf0, bf1;
            wmma::load_matrix_sync(af, &As[rt * 16 * HSTR + k16 * 16], HSTR);
            wmma::load_matrix_sync(bf0, &Bs[k16 * 16 * HSTR + ct * 32], HSTR);
            wmma::load_matrix_sync(bf1, &Bs[k16 * 16 * HSTR + ct * 32 + 16], HSTR);
            wmma::mma_sync(c0, af, bf0, c0);
            wmma::mma_sync(c1, af, bf1, c1);
        }
        __syncthreads();
    }

    // epilogue: fp32 frag -> fp16 frag (same element mapping) -> direct global store
    wmma::fragment<wmma::accumulator, 16, 16, 16, __half> h0, h1;
#pragma unroll
    for (int i = 0; i < c0.num_elements; i++) {
        h0.x[i] = __float2half_rn(c0.x[i]);
        h1.x[i] = __float2half_rn(c1.x[i]);
    }
    __half* C = g_we + (size_t)bm * GBM * (Hh * Hh) + bn * GBN + (size_t)(rt * 16) * (Hh * Hh);
    wmma::store_matrix_sync(C + ct * 32,      h0, Hh * Hh, wmma::mem_row_major);
    wmma::store_matrix_sync(C + ct * 32 + 16, h1, Hh * Hh, wmma::mem_row_major);
}

// ---------------- degree / batch counts ----------------
__global__ void k_deg(const int* __restrict__ dst) {
    int e = blockIdx.x * blockDim.x + threadIdx.x;
    if (e < Ee) atomicAdd(&g_deg[dst[e]], 1.0f);
}
__global__ void k_cnt(const int* __restrict__ batch) {
    int n = blockIdx.x * blockDim.x + threadIdx.x;
    if (n < Nn) atomicAdd(&g_cnt[batch[n]], 1);
}
__global__ void k_scan() {
    int t = threadIdx.x;
    if (t == 0) {
        g_ptr[0] = 0;
        for (int b = 0; b < Bb; b++) g_ptr[b + 1] = g_ptr[b] + g_cnt[b];
    }
    for (int i = t; i < Bb * Hh; i += 256) { g_hs[i] = 0.0f; g_cs[i] = 0.0f; }
    for (int i = t; i < Bb * 2 * Hh; i += 256) g_qstar[i] = 0.0f;
}

// ---------------- per-edge matvec + scatter: 8 threads/edge, register accumulation ----
__global__ __launch_bounds__(256)
void k_msg(const int* __restrict__ src, const int* __restrict__ dst) {
    __shared__ float xs[32][Hh];
    __shared__ int   sid[32], did[32];
    int t = threadIdx.x;
    int e0 = blockIdx.x * 32;
    if (t < 32) { sid[t] = src[e0 + t]; did[t] = dst[e0 + t]; }
    __syncthreads();
#pragma unroll
    for (int p = 0; p < 8; p++) {
        int idx = p * 256 + t;
        int le2 = idx >> 6, c = idx & 63;
        xs[le2][c] = g_X[sid[le2] * Hh + c];
    }
    __syncthreads();

    int le = t >> 3;
    int c8 = (t & 7) * 8;
    const __half* we = g_we + (size_t)(e0 + le) * Hh * Hh + c8;
    float acc[8] = {};
#pragma unroll 8
    for (int i = 0; i < Hh; i++) {
        float xv = xs[le][i];
        uint4 raw = __ldcs((const uint4*)(we + i * Hh));
        const __half2* hp = (const __half2*)&raw;
#pragma unroll
        for (int j = 0; j < 4; j++) {
            float2 f = __half22float2(hp[j]);
            acc[2 * j]     = fmaf(xv, f.x, acc[2 * j]);
            acc[2 * j + 1] = fmaf(xv, f.y, acc[2 * j + 1]);
        }
    }
    float* ap = &g_agg[did[le] * Hh + c8];
#pragma unroll
    for (int j = 0; j < 8; j++) atomicAdd(&ap[j], acc[j]);
}

// ---------------- fused GRU (round-8 form, fp32 scalar weights) ----------------
__global__ void k_gru(const float* __restrict__ cr, const float* __restrict__ cb,
                      const float* __restrict__ wih, const float* __restrict__ whh,
                      const float* __restrict__ bih, const float* __restrict__ bhh) {
    __shared__ float xs[Hh], ms[Hh], gi[3 * Hh], gh[3 * Hh];
    int n = blockIdx.x, t = threadIdx.x;           // 192 threads
    if (t < Hh) xs[t] = g_X[n * Hh + t];
    __syncthreads();
    if (t < Hh) {
        float d = fmaxf(g_deg[n], 1.0f);
        float acc = g_agg[n * Hh + t] / d + cb[t];
        g_agg[n * Hh + t] = 0.0f;
#pragma unroll
        for (int i = 0; i < Hh; i++) acc = fmaf(xs[i], cr[i * Hh + t], acc);
        ms[t] = fmaxf(acc, 0.0f);
    }
    __syncthreads();
    {
        float a = bih[t], c = bhh[t];
#pragma unroll
        for (int i = 0; i < Hh; i++) {
            a = fmaf(ms[i], wih[i * 3 * Hh + t], a);
            c = fmaf(xs[i], whh[i * 3 * Hh + t], c);
        }
        gi[t] = a; gh[t] = c;
    }
    __syncthreads();
    if (t < Hh) {
        float r = sigf(gi[t] + gh[t]);
        float z = sigf(gi[Hh + t] + gh[Hh + t]);
        float ng = tanhf(gi[2 * Hh + t] + r * gh[2 * Hh + t]);
        g_X[n * Hh + t] = (1.0f - z) * ng + z * xs[t];
    }
}

// ---------------- Set2Set LSTM step ----------------
__global__ void k_lstm(const float* __restrict__ wih, const float* __restrict__ whh,
                       const float* __restrict__ bih, const float* __restrict__ bhh) {
    __shared__ float qs[2 * Hh], hr[Hh], g[4 * Hh];
    int b = blockIdx.x, t = threadIdx.x;           // 256 threads
    if (t < 2 * Hh) qs[t] = g_qstar[b * 2 * Hh + t];
    if (t < Hh) hr[t] = g_hs[b * Hh + t];
    __syncthreads();
    {
        float a = bih[t] + bhh[t];
#pragma unroll
        for (int i = 0; i < 2 * Hh; i++) a = fmaf(qs[i], wih[i * 4 * Hh + t], a);
#pragma unroll
        for (int i = 0; i < Hh; i++) a = fmaf(hr[i], whh[i * 4 * Hh + t], a);
        g[t] = a;
    }
    __syncthreads();
    if (t < Hh) {
        float ii = sigf(g[t]);
        float ff = sigf(g[Hh + t]);
        float gg = tanhf(g[2 * Hh + t]);
        float oo = sigf(g[3 * Hh + t]);
        float c2 = ff * g_cs[b * Hh + t] + ii * gg;
        float h2 = oo * tanhf(c2);
        g_cs[b * Hh + t] = c2;
        g_hs[b * Hh + t] = h2;
        g_qstar[b * 2 * Hh + t] = h2;
    }
}

// ---------------- en[n] = dot(X[n], hs[batch[n]]) ----------------
__global__ void k_en(const int* __restrict__ batch) {
    __shared__ float red[2];
    int n = blockIdx.x, o = threadIdx.x;           // 64 threads
    int b = batch[n];
    float v = g_X[n * Hh + o] * g_hs[b * Hh + o];
#pragma unroll
    for (int s = 16; s > 0; s >>= 1) v += __shfl_down_sync(0xffffffffu, v, s);
    if ((o & 31) == 0) red[o >> 5] = v;
    __syncthreads();
    if (o == 0) g_en[n] = red[0] + red[1];
}

// ---------------- per-graph softmax + weighted readout ----------------
__global__ __launch_bounds__(256)
void k_pool() {
    __shared__ float red[256];
    __shared__ float part[4][Hh];
    int b = blockIdx.x, t = threadIdx.x;           // 256 threads
    int s = g_ptr[b], e = g_ptr[b + 1];
    float m = -1e30f;
    for (int n = s + t; n < e; n += 256) m = fmaxf(m, g_en[n]);
    red[t] = m; __syncthreads();
    for (int st = 128; st > 0; st >>= 1) { if (t < st) red[t] = fmaxf(red[t], red[t + st]); __syncthreads(); }
    float mx = red[0]; __syncthreads();
    float ss = 0.0f;
    for (int n = s + t; n < e; n += 256) ss += expf(g_en[n] - mx);
    red[t] = ss; __syncthreads();
    for (int st = 128; st > 0; st >>= 1) { if (t < st) red[t] += red[t + st]; __syncthreads(); }
    float inv = 1.0f / (red[0] + 1e-16f);
    int ch = t >> 6, col = t & 63;
    float acc = 0.0f;
    for (int n = s + ch; n < e; n += 4) {
        float a = expf(g_en[n] - mx) * inv;
        acc = fmaf(a, g_X[n * Hh + col], acc);
    }
    part[ch][col] = acc; __syncthreads();
    if (t < Hh)
        g_qstar[b * 2 * Hh + Hh + t] = part[0][t] + part[1][t] + part[2][t] + part[3][t];
}

// ---------------- head ----------------
__global__ void k_final(const float* __restrict__ w1, const float* __restrict__ b1,
                        const float* __restrict__ w2, const float* __restrict__ b2,
                        float* __restrict__ out) {
    __shared__ float qs[2 * Hh], red[Hh];
    int b = blockIdx.x, t = threadIdx.x;           // 64 threads
    qs[t] = g_qstar[b * 2 * Hh + t];
    qs[Hh + t] = g_qstar[b * 2 * Hh + Hh + t];
    __syncthreads();
    float a = b1[t];
#pragma unroll
    for (int i = 0; i < 2 * Hh; i++) a = fmaf(qs[i], w1[i * Hh + t], a);
    a = fmaxf(a, 0.0f);
    red[t] = a * w2[t];
    __syncthreads();
    for (int st = 32; st > 0; st >>= 1) { if (t < st) red[t] += red[t + st]; __syncthreads(); }
    if (t == 0) out[b] = red[0] + b2[0];
}

// ---------------- launcher ----------------
extern "C" void kernel_launch(void* const* d_in, const int* in_sizes, int n_in,
                              void* d_out, int out_size) {
    const float* x         = (const float*)d_in[0];
    const int*   ei        = (const int*)d_in[1];
    const int*   batch     = (const int*)d_in[2];
    const float* edge_attr = (const float*)d_in[3];
    const float* lin0_w = (const float*)d_in[4];
    const float* lin0_b = (const float*)d_in[5];
    const float* nn_w1  = (const float*)d_in[6];
    const float* nn_b1  = (const float*)d_in[7];
    const float* nn_w2  = (const float*)d_in[8];
    const float* nn_b2  = (const float*)d_in[9];
    const float* conv_root = (const float*)d_in[10];
    const float* conv_bias = (const float*)d_in[11];
    const float* gru_wih = (const float*)d_in[12];
    const float* gru_whh = (const float*)d_in[13];
    const float* gru_bih = (const float*)d_in[14];
    const float* gru_bhh = (const float*)d_in[15];
    const float* lstm_wih = (const float*)d_in[16];
    const float* lstm_whh = (const float*)d_in[17];
    const float* lstm_bih = (const float*)d_in[18];
    const float* lstm_bhh = (const float*)d_in[19];
    const float* lin1_w = (const float*)d_in[20];
    const float* lin1_b = (const float*)d_in[21];
    const float* lin2_w = (const float*)d_in[22];
    const float* lin2_b = (const float*)d_in[23];

    const int* src = ei;
    const int* dst = ei + Ee;

    void *p_deg, *p_cnt;
    cudaGetSymbolAddress(&p_deg, g_deg);
    cudaGetSymbolAddress(&p_cnt, g_cnt);
    cudaMemsetAsync(p_deg, 0, Nn * sizeof(float), 0);
    cudaMemsetAsync(p_cnt, 0, Bb * sizeof(int), 0);

    // launch #4 (k_gemm_we) is the ncu-profiled one
    k_prep<<<512, 256>>>(nn_w2);                                     // 1
    k_lin0<<<Nn, Hh>>>(x, lin0_w, lin0_b);                           // 2
    k_mlp1<<<Ee, HID>>>(edge_attr, nn_w1, nn_b1);                    // 3
    k_gemm_we<<<dim3((Hh * Hh) / GBN, Ee / GBM), 256>>>(nn_b2);      // 4 <- profiled
    k_deg<<<(Ee + 255) / 256, 256>>>(dst);                           // 5
    k_cnt<<<(Nn + 255) / 256, 256>>>(batch);                         // 6
    k_scan<<<1, 256>>>();                                            // 7

    for (int it = 0; it < 3; it++) {
        k_msg<<<Ee / 32, 256>>>(src, dst);
        k_gru<<<Nn, 3 * Hh>>>(conv_root, conv_bias, gru_wih, gru_whh, gru_bih, gru_bhh);
    }

    for (int st = 0; st < 3; st++) {
        k_lstm<<<Bb, 4 * Hh>>>(lstm_wih, lstm_whh, lstm_bih, lstm_bhh);
        k_en<<<Nn, Hh>>>(batch);
        k_pool<<<Bb, 256>>>();
    }

    k_final<<<Bb, Hh>>>(lin1_w, lin1_b, lin2_w, lin2_b, (float*)d_out);
}

// round 12
// speedup vs baseline: 1.0530x; 1.0530x over previous
#include <cuda_runtime.h>
#include <cuda_fp16.h>
#include <mma.h>
#include <math.h>
#include <stdint.h>

using namespace nvcuda;

#define Nn  20000
#define Ee  80000
#define Hh  64
#define NFf 32
#define Bb  64
#define HID 128

// ---------------- device scratch (no allocations allowed) ----------------
__device__ float  g_X[Nn * Hh];
__device__ float  g_agg[Nn * Hh];              // zeroed at load; k_gru re-zeroes after use
__device__ __half g_hid[Ee * HID];             // edge MLP hidden (fp16)
__device__ __half g_w2h[HID * Hh * Hh];        // W2 in fp16 (1 MB)
__device__ __half g_we[(size_t)Ee * Hh * Hh];  // 655 MB edge weights (fp16)
__device__ float  g_deg[Nn];
__device__ int    g_cnt[Bb];
__device__ int    g_ptr[Bb + 1];
__device__ float  g_en[Nn];
__device__ float  g_hs[Bb * Hh];
__device__ float  g_cs[Bb * Hh];
__device__ float  g_qstar[Bb * 2 * Hh];

__device__ __forceinline__ float sigf(float x) { return 1.0f / (1.0f + expf(-x)); }

// ---------------- prep: W2 -> fp16 ----------------
__global__ void k_prep(const float* __restrict__ w2) {
    int i4 = (blockIdx.x * 256 + threadIdx.x) * 4;
    float4 v = *(const float4*)&w2[i4];
    *(__half2*)&g_w2h[i4]     = __floats2half2_rn(v.x, v.y);
    *(__half2*)&g_w2h[i4 + 2] = __floats2half2_rn(v.z, v.w);
}

// ---------------- lin0: X = relu(x @ W0 + b0) ----------------
__global__ void k_lin0(const float* __restrict__ x, const float* __restrict__ w,
                       const float* __restrict__ b) {
    __shared__ float xs[NFf];
    int n = blockIdx.x, o = threadIdx.x;           // 64 threads
    if (o < NFf) xs[o] = x[n * NFf + o];
    __syncthreads();
    float acc = b[o];
#pragma unroll
    for (int i = 0; i < NFf; i++) acc = fmaf(xs[i], w[i * Hh + o], acc);
    g_X[n * Hh + o] = fmaxf(acc, 0.0f);
}

// ---------------- edge MLP layer 1: hid = fp16(relu(edge_attr @ W1 + b1)) ----------------
__global__ void k_mlp1(const float* __restrict__ ea, const float* __restrict__ w,
                       const float* __restrict__ b) {
    __shared__ float es[Hh];
    int e = blockIdx.x, j = threadIdx.x;           // 128 threads
    if (j < Hh) es[j] = ea[e * Hh + j];
    __syncthreads();
    float acc = b[j];
#pragma unroll
    for (int i = 0; i < Hh; i++) acc = fmaf(es[i], w[i * HID + j], acc);
    g_hid[e * HID + j] = __float2half_rn(fmaxf(acc, 0.0f));
}

// ---------------- big GEMM (fp16 HMMA, round-4 shape, occ-forced): we = fp16(hid @ W2 + b2) ----
#define GBM 64
#define GBN 64
#define GBK 64
#define HSTR 72
#define BSTRc 68
__global__ __launch_bounds__(256, 5)
void k_gemm_we(const float* __restrict__ bias) {
    __shared__ __half As[GBM * HSTR];     // 64 x 72 half
    __shared__ __half Bs[GBK * HSTR];     // 64 x 72 half
    __shared__ float  Cs[GBM * BSTRc];    // 64 x 68 float (epilogue)

    int bn = blockIdx.x;            // 0..63  (col tile)
    int bm = blockIdx.y;            // 0..1249 (row tile)
    int t  = threadIdx.x;           // 256
    int wid = t >> 5;
    int rt = wid & 3;               // 16-row tile
    int ct = wid >> 2;              // 32-col half

    wmma::fragment<wmma::accumulator, 16, 16, 16, float> c0, c1;
    wmma::fill_fragment(c0, 0.0f);
    wmma::fill_fragment(c1, 0.0f);

    const __half* A = g_hid + (size_t)bm * GBM * HID;
    const __half* Bg = g_w2h + bn * GBN;

    int lr = t >> 3;                // 0..31
    int lc = (t & 7) * 8;           // half-index, 8 halfs = 16B

    for (int kt = 0; kt < HID; kt += GBK) {
        *(float4*)&As[lr * HSTR + lc]        = *(const float4*)&A[lr * HID + kt + lc];
        *(float4*)&As[(lr + 32) * HSTR + lc] = *(const float4*)&A[(lr + 32) * HID + kt + lc];
        *(float4*)&Bs[lr * HSTR + lc]        = *(const float4*)&Bg[(size_t)(kt + lr) * (Hh * Hh) + lc];
        *(float4*)&Bs[(lr + 32) * HSTR + lc] = *(const float4*)&Bg[(size_t)(kt + lr + 32) * (Hh * Hh) + lc];
        __syncthreads();
#pragma unroll
        for (int k16 = 0; k16 < GBK / 16; k16++) {
            wmma::fragment<wmma::matrix_a, 16, 16, 16, __half, wmma::row_major> af;
            wmma::fragment<wmma::matrix_b, 16, 16, 16, __half, wmma::row_major> bf0, bf1;
            wmma::load_matrix_sync(af, &As[rt * 16 * HSTR + k16 * 16], HSTR);
            wmma::load_matrix_sync(bf0, &Bs[k16 * 16 * HSTR + ct * 32], HSTR);
            wmma::load_matrix_sync(bf1, &Bs[k16 * 16 * HSTR + ct * 32 + 16], HSTR);
            wmma::mma_sync(c0, af, bf0, c0);
            wmma::mma_sync(c1, af, bf1, c1);
        }
        __syncthreads();
    }

    wmma::store_matrix_sync(&Cs[rt * 16 * BSTRc + ct * 32], c0, BSTRc, wmma::mem_row_major);
    wmma::store_matrix_sync(&Cs[rt * 16 * BSTRc + ct * 32 + 16], c1, BSTRc, wmma::mem_row_major);
    __syncthreads();

    __half* C = g_we + (size_t)bm * GBM * (Hh * Hh) + bn * GBN;
#pragma unroll
    for (int p = 0; p < 4; p++) {
        int idx = p * 1024 + t * 4;
        int r = idx >> 6, c = idx & 63;
        float4 v = *(float4*)&Cs[r * BSTRc + c];
        int cg = bn * GBN + c;
        v.x += bias[cg + 0]; v.y += bias[cg + 1];
        v.z += bias[cg + 2]; v.w += bias[cg + 3];
        __half2 h0 = __floats2half2_rn(v.x, v.y);
        __half2 h1 = __floats2half2_rn(v.z, v.w);
        *(__half2*)&C[(size_t)r * (Hh * Hh) + c] = h0;
        *(__half2*)&C[(size_t)r * (Hh * Hh) + c + 2] = h1;
    }
}

// ---------------- degree / batch counts ----------------
__global__ void k_deg(const int* __restrict__ dst) {
    int e = blockIdx.x * blockDim.x + threadIdx.x;
    if (e < Ee) atomicAdd(&g_deg[dst[e]], 1.0f);
}
__global__ void k_cnt(const int* __restrict__ batch) {
    int n = blockIdx.x * blockDim.x + threadIdx.x;
    if (n < Nn) atomicAdd(&g_cnt[batch[n]], 1);
}
__global__ void k_scan() {
    int t = threadIdx.x;
    if (t == 0) {
        g_ptr[0] = 0;
        for (int b = 0; b < Bb; b++) g_ptr[b + 1] = g_ptr[b] + g_cnt[b];
    }
    for (int i = t; i < Bb * Hh; i += 256) { g_hs[i] = 0.0f; g_cs[i] = 0.0f; }
    for (int i = t; i < Bb * 2 * Hh; i += 256) g_qstar[i] = 0.0f;
}

// ---------------- per-edge matvec + scatter: 8 threads/edge, deeper LDG queue ----
__global__ __launch_bounds__(256)
void k_msg(const int* __restrict__ src, const int* __restrict__ dst) {
    __shared__ float xs[32][Hh];
    __shared__ int   sid[32], did[32];
    int t = threadIdx.x;
    int e0 = blockIdx.x * 32;
    if (t < 32) { sid[t] = src[e0 + t]; did[t] = dst[e0 + t]; }
    __syncthreads();
#pragma unroll
    for (int p = 0; p < 8; p++) {
        int idx = p * 256 + t;
        int le2 = idx >> 6, c = idx & 63;
        xs[le2][c] = g_X[sid[le2] * Hh + c];
    }
    __syncthreads();

    int le = t >> 3;
    int c8 = (t & 7) * 8;
    const __half* we = g_we + (size_t)(e0 + le) * Hh * Hh + c8;
    float acc[8] = {};
#pragma unroll 16
    for (int i = 0; i < Hh; i++) {
        float xv = xs[le][i];
        uint4 raw = __ldcs((const uint4*)(we + i * Hh));
        const __half2* hp = (const __half2*)&raw;
#pragma unroll
        for (int j = 0; j < 4; j++) {
            float2 f = __half22float2(hp[j]);
            acc[2 * j]     = fmaf(xv, f.x, acc[2 * j]);
            acc[2 * j + 1] = fmaf(xv, f.y, acc[2 * j + 1]);
        }
    }
    float* ap = &g_agg[did[le] * Hh + c8];
#pragma unroll
    for (int j = 0; j < 8; j++) atomicAdd(&ap[j], acc[j]);
}

// ---------------- fused m = relu(agg/deg + X@root + cb) ; X = GRU(m, X) ----------------
__global__ void k_gru(const float* __restrict__ cr, const float* __restrict__ cb,
                      const float* __restrict__ wih, const float* __restrict__ whh,
                      const float* __restrict__ bih, const float* __restrict__ bhh) {
    __shared__ float xs[Hh], ms[Hh], gi[3 * Hh], gh[3 * Hh];
    int n = blockIdx.x, t = threadIdx.x;           // 192 threads
    if (t < Hh) xs[t] = g_X[n * Hh + t];
    __syncthreads();
    if (t < Hh) {
        float d = fmaxf(g_deg[n], 1.0f);
        float acc = g_agg[n * Hh + t] / d + cb[t];
        g_agg[n * Hh + t] = 0.0f;
#pragma unroll
        for (int i = 0; i < Hh; i++) acc = fmaf(xs[i], cr[i * Hh + t], acc);
        ms[t] = fmaxf(acc, 0.0f);
    }
    __syncthreads();
    {
        float a = bih[t], c = bhh[t];
#pragma unroll
        for (int i = 0; i < Hh; i++) {
            a = fmaf(ms[i], wih[i * 3 * Hh + t], a);
            c = fmaf(xs[i], whh[i * 3 * Hh + t], c);
        }
        gi[t] = a; gh[t] = c;
    }
    __syncthreads();
    if (t < Hh) {
        float r = sigf(gi[t] + gh[t]);
        float z = sigf(gi[Hh + t] + gh[Hh + t]);
        float ng = tanhf(gi[2 * Hh + t] + r * gh[2 * Hh + t]);
        g_X[n * Hh + t] = (1.0f - z) * ng + z * xs[t];
    }
}

// ---------------- Set2Set LSTM step ----------------
__global__ void k_lstm(const float* __restrict__ wih, const float* __restrict__ whh,
                       const float* __restrict__ bih, const float* __restrict__ bhh) {
    __shared__ float qs[2 * Hh], hr[Hh], g[4 * Hh];
    int b = blockIdx.x, t = threadIdx.x;           // 256 threads
    if (t < 2 * Hh) qs[t] = g_qstar[b * 2 * Hh + t];
    if (t < Hh) hr[t] = g_hs[b * Hh + t];
    __syncthreads();
    {
        float a = bih[t] + bhh[t];
#pragma unroll
        for (int i = 0; i < 2 * Hh; i++) a = fmaf(qs[i], wih[i * 4 * Hh + t], a);
#pragma unroll
        for (int i = 0; i < Hh; i++) a = fmaf(hr[i], whh[i * 4 * Hh + t], a);
        g[t] = a;
    }
    __syncthreads();
    if (t < Hh) {
        float ii = sigf(g[t]);
        float ff = sigf(g[Hh + t]);
        float gg = tanhf(g[2 * Hh + t]);
        float oo = sigf(g[3 * Hh + t]);
        float c2 = ff * g_cs[b * Hh + t] + ii * gg;
        float h2 = oo * tanhf(c2);
        g_cs[b * Hh + t] = c2;
        g_hs[b * Hh + t] = h2;
        g_qstar[b * 2 * Hh + t] = h2;
    }
}

// ---------------- en[n] = dot(X[n], hs[batch[n]]) ----------------
__global__ void k_en(const int* __restrict__ batch) {
    __shared__ float red[2];
    int n = blockIdx.x, o = threadIdx.x;           // 64 threads
    int b = batch[n];
    float v = g_X[n * Hh + o] * g_hs[b * Hh + o];
#pragma unroll
    for (int s = 16; s > 0; s >>= 1) v += __shfl_down_sync(0xffffffffu, v, s);
    if ((o & 31) == 0) red[o >> 5] = v;
    __syncthreads();
    if (o == 0) g_en[n] = red[0] + red[1];
}

// ---------------- per-graph softmax + weighted readout ----------------
__global__ __launch_bounds__(256)
void k_pool() {
    __shared__ float red[256];
    __shared__ float part[4][Hh];
    int b = blockIdx.x, t = threadIdx.x;           // 256 threads
    int s = g_ptr[b], e = g_ptr[b + 1];
    float m = -1e30f;
    for (int n = s + t; n < e; n += 256) m = fmaxf(m, g_en[n]);
    red[t] = m; __syncthreads();
    for (int st = 128; st > 0; st >>= 1) { if (t < st) red[t] = fmaxf(red[t], red[t + st]); __syncthreads(); }
    float mx = red[0]; __syncthreads();
    float ss = 0.0f;
    for (int n = s + t; n < e; n += 256) ss += expf(g_en[n] - mx);
    red[t] = ss; __syncthreads();
    for (int st = 128; st > 0; st >>= 1) { if (t < st) red[t] += red[t + st]; __syncthreads(); }
    float inv = 1.0f / (red[0] + 1e-16f);
    int ch = t >> 6, col = t & 63;
    float acc = 0.0f;
    for (int n = s + ch; n < e; n += 4) {
        float a = expf(g_en[n] - mx) * inv;
        acc = fmaf(a, g_X[n * Hh + col], acc);
    }
    part[ch][col] = acc; __syncthreads();
    if (t < Hh)
        g_qstar[b * 2 * Hh + Hh + t] = part[0][t] + part[1][t] + part[2][t] + part[3][t];
}

// ---------------- head ----------------
__global__ void k_final(const float* __restrict__ w1, const float* __restrict__ b1,
                        const float* __restrict__ w2, const float* __restrict__ b2,
                        float* __restrict__ out) {
    __shared__ float qs[2 * Hh], red[Hh];
    int b = blockIdx.x, t = threadIdx.x;           // 64 threads
    qs[t] = g_qstar[b * 2 * Hh + t];
    qs[Hh + t] = g_qstar[b * 2 * Hh + Hh + t];
    __syncthreads();
    float a = b1[t];
#pragma unroll
    for (int i = 0; i < 2 * Hh; i++) a = fmaf(qs[i], w1[i * Hh + t], a);
    a = fmaxf(a, 0.0f);
    red[t] = a * w2[t];
    __syncthreads();
    for (int st = 32; st > 0; st >>= 1) { if (t < st) red[t] += red[t + st]; __syncthreads(); }
    if (t == 0) out[b] = red[0] + b2[0];
}

// ---------------- launcher ----------------
extern "C" void kernel_launch(void* const* d_in, const int* in_sizes, int n_in,
                              void* d_out, int out_size) {
    const float* x         = (const float*)d_in[0];
    const int*   ei        = (const int*)d_in[1];
    const int*   batch     = (const int*)d_in[2];
    const float* edge_attr = (const float*)d_in[3];
    const float* lin0_w = (const float*)d_in[4];
    const float* lin0_b = (const float*)d_in[5];
    const float* nn_w1  = (const float*)d_in[6];
    const float* nn_b1  = (const float*)d_in[7];
    const float* nn_w2  = (const float*)d_in[8];
    const float* nn_b2  = (const float*)d_in[9];
    const float* conv_root = (const float*)d_in[10];
    const float* conv_bias = (const float*)d_in[11];
    const float* gru_wih = (const float*)d_in[12];
    const float* gru_whh = (const float*)d_in[13];
    const float* gru_bih = (const float*)d_in[14];
    const float* gru_bhh = (const float*)d_in[15];
    const float* lstm_wih = (const float*)d_in[16];
    const float* lstm_whh = (const float*)d_in[17];
    const float* lstm_bih = (const float*)d_in[18];
    const float* lstm_bhh = (const float*)d_in[19];
    const float* lin1_w = (const float*)d_in[20];
    const float* lin1_b = (const float*)d_in[21];
    const float* lin2_w = (const float*)d_in[22];
    const float* lin2_b = (const float*)d_in[23];

    const int* src = ei;
    const int* dst = ei + Ee;

    void *p_deg, *p_cnt;
    cudaGetSymbolAddress(&p_deg, g_deg);
    cudaGetSymbolAddress(&p_cnt, g_cnt);
    cudaMemsetAsync(p_deg, 0, Nn * sizeof(float), 0);
    cudaMemsetAsync(p_cnt, 0, Bb * sizeof(int), 0);

    // launch #4 (k_gemm_we) is the ncu-profiled one
    k_prep<<<512, 256>>>(nn_w2);                                     // 1
    k_lin0<<<Nn, Hh>>>(x, lin0_w, lin0_b);                           // 2
    k_mlp1<<<Ee, HID>>>(edge_attr, nn_w1, nn_b1);                    // 3
    k_gemm_we<<<dim3((Hh * Hh) / GBN, Ee / GBM), 256>>>(nn_b2);      // 4 <- profiled
    k_deg<<<(Ee + 255) / 256, 256>>>(dst);                           // 5
    k_cnt<<<(Nn + 255) / 256, 256>>>(batch);                         // 6
    k_scan<<<1, 256>>>();                                            // 7

    for (int it = 0; it < 3; it++) {
        k_msg<<<Ee / 32, 256>>>(src, dst);
        k_gru<<<Nn, 3 * Hh>>>(conv_root, conv_bias, gru_wih, gru_whh, gru_bih, gru_bhh);
    }

    for (int st = 0; st < 3; st++) {
        k_lstm<<<Bb, 4 * Hh>>>(lstm_wih, lstm_whh, lstm_bih, lstm_bhh);
        k_en<<<Nn, Hh>>>(batch);
        k_pool<<<Bb, 256>>>();
    }

    k_final<<<Bb, Hh>>>(lin1_w, lin1_b, lin2_w, lin2_b, (float*)d_out);
}

// round 13
// speedup vs baseline: 1.1118x; 1.0559x over previous
#include <cuda_runtime.h>
#include <cuda_fp16.h>
#include <mma.h>
#include <math.h>
#include <stdint.h>

using namespace nvcuda;

#define Nn  20000
#define Ee  80000
#define Hh  64
#define NFf 32
#define Bb  64
#define HID 128

// ---------------- device scratch (no allocations allowed) ----------------
__device__ float  g_X[Nn * Hh];
__device__ float  g_agg[Nn * Hh];              // zeroed at load; k_gru re-zeroes after use
__device__ __half g_hid[Ee * HID];             // edge MLP hidden (fp16)
__device__ __half g_w2h[HID * Hh * Hh];        // W2 in fp16 (1 MB)
__device__ __half g_we[(size_t)Ee * Hh * Hh];  // 655 MB edge weights (fp16)
__device__ float  g_deg[Nn];
__device__ int    g_cnt[Bb];
__device__ int    g_ptr[Bb + 1];
__device__ float  g_en[Nn];
__device__ float  g_hs[Bb * Hh];
__device__ float  g_cs[Bb * Hh];
__device__ float  g_qstar[Bb * 2 * Hh];

__device__ __forceinline__ float sigf(float x) { return 1.0f / (1.0f + expf(-x)); }

// ---------------- prep: W2 -> fp16 ----------------
__global__ void k_prep(const float* __restrict__ w2) {
    int i4 = (blockIdx.x * 256 + threadIdx.x) * 4;
    float4 v = *(const float4*)&w2[i4];
    *(__half2*)&g_w2h[i4]     = __floats2half2_rn(v.x, v.y);
    *(__half2*)&g_w2h[i4 + 2] = __floats2half2_rn(v.z, v.w);
}

// ---------------- lin0: X = relu(x @ W0 + b0) ----------------
__global__ void k_lin0(const float* __restrict__ x, const float* __restrict__ w,
                       const float* __restrict__ b) {
    __shared__ float xs[NFf];
    int n = blockIdx.x, o = threadIdx.x;           // 64 threads
    if (o < NFf) xs[o] = x[n * NFf + o];
    __syncthreads();
    float acc = b[o];
#pragma unroll
    for (int i = 0; i < NFf; i++) acc = fmaf(xs[i], w[i * Hh + o], acc);
    g_X[n * Hh + o] = fmaxf(acc, 0.0f);
}

// ---------------- edge MLP layer 1: hid = fp16(relu(edge_attr @ W1 + b1)) ----------------
__global__ void k_mlp1(const float* __restrict__ ea, const float* __restrict__ w,
                       const float* __restrict__ b) {
    __shared__ float es[Hh];
    int e = blockIdx.x, j = threadIdx.x;           // 128 threads
    if (j < Hh) es[j] = ea[e * Hh + j];
    __syncthreads();
    float acc = b[j];
#pragma unroll
    for (int i = 0; i < Hh; i++) acc = fmaf(es[i], w[i * HID + j], acc);
    g_hid[e * HID + j] = __float2half_rn(fmaxf(acc, 0.0f));
}

// ---------------- big GEMM (fp16 HMMA, round-8 exact form): we = fp16(hid @ W2 + b2) ----------
#define GBM 64
#define GBN 64
#define GBK 64
#define HSTR 72
#define BSTRc 68
__global__ __launch_bounds__(256)
void k_gemm_we(const float* __restrict__ bias) {
    __shared__ __half As[GBM * HSTR];     // 64 x 72 half
    __shared__ __half Bs[GBK * HSTR];     // 64 x 72 half
    __shared__ float  Cs[GBM * BSTRc];    // 64 x 68 float (epilogue)

    int bn = blockIdx.x;            // 0..63  (col tile)
    int bm = blockIdx.y;            // 0..1249 (row tile)
    int t  = threadIdx.x;           // 256
    int wid = t >> 5;
    int rt = wid & 3;               // 16-row tile
    int ct = wid >> 2;              // 32-col half

    wmma::fragment<wmma::accumulator, 16, 16, 16, float> c0, c1;
    wmma::fill_fragment(c0, 0.0f);
    wmma::fill_fragment(c1, 0.0f);

    const __half* A = g_hid + (size_t)bm * GBM * HID;
    const __half* Bg = g_w2h + bn * GBN;

    int lr = t >> 3;                // 0..31
    int lc = (t & 7) * 8;           // half-index, 8 halfs = 16B

    for (int kt = 0; kt < HID; kt += GBK) {
        *(float4*)&As[lr * HSTR + lc]        = *(const float4*)&A[lr * HID + kt + lc];
        *(float4*)&As[(lr + 32) * HSTR + lc] = *(const float4*)&A[(lr + 32) * HID + kt + lc];
        *(float4*)&Bs[lr * HSTR + lc]        = *(const float4*)&Bg[(size_t)(kt + lr) * (Hh * Hh) + lc];
        *(float4*)&Bs[(lr + 32) * HSTR + lc] = *(const float4*)&Bg[(size_t)(kt + lr + 32) * (Hh * Hh) + lc];
        __syncthreads();
#pragma unroll
        for (int k16 = 0; k16 < GBK / 16; k16++) {
            wmma::fragment<wmma::matrix_a, 16, 16, 16, __half, wmma::row_major> af;
            wmma::fragment<wmma::matrix_b, 16, 16, 16, __half, wmma::row_major> bf0, bf1;
            wmma::load_matrix_sync(af, &As[rt * 16 * HSTR + k16 * 16], HSTR);
            wmma::load_matrix_sync(bf0, &Bs[k16 * 16 * HSTR + ct * 32], HSTR);
            wmma::load_matrix_sync(bf1, &Bs[k16 * 16 * HSTR + ct * 32 + 16], HSTR);
            wmma::mma_sync(c0, af, bf0, c0);
            wmma::mma_sync(c1, af, bf1, c1);
        }
        __syncthreads();
    }

    wmma::store_matrix_sync(&Cs[rt * 16 * BSTRc + ct * 32], c0, BSTRc, wmma::mem_row_major);
    wmma::store_matrix_sync(&Cs[rt * 16 * BSTRc + ct * 32 + 16], c1, BSTRc, wmma::mem_row_major);
    __syncthreads();

    __half* C = g_we + (size_t)bm * GBM * (Hh * Hh) + bn * GBN;
#pragma unroll
    for (int p = 0; p < 4; p++) {
        int idx = p * 1024 + t * 4;
        int r = idx >> 6, c = idx & 63;
        float4 v = *(float4*)&Cs[r * BSTRc + c];
        int cg = bn * GBN + c;
        v.x += bias[cg + 0]; v.y += bias[cg + 1];
        v.z += bias[cg + 2]; v.w += bias[cg + 3];
        __half2 h0 = __floats2half2_rn(v.x, v.y);
        __half2 h1 = __floats2half2_rn(v.z, v.w);
        *(__half2*)&C[(size_t)r * (Hh * Hh) + c] = h0;
        *(__half2*)&C[(size_t)r * (Hh * Hh) + c + 2] = h1;
    }
}

// ---------------- degree / batch counts ----------------
__global__ void k_deg(const int* __restrict__ dst) {
    int e = blockIdx.x * blockDim.x + threadIdx.x;
    if (e < Ee) atomicAdd(&g_deg[dst[e]], 1.0f);
}
__global__ void k_cnt(const int* __restrict__ batch) {
    int n = blockIdx.x * blockDim.x + threadIdx.x;
    if (n < Nn) atomicAdd(&g_cnt[batch[n]], 1);
}
__global__ void k_scan() {
    int t = threadIdx.x;
    if (t == 0) {
        g_ptr[0] = 0;
        for (int b = 0; b < Bb; b++) g_ptr[b + 1] = g_ptr[b] + g_cnt[b];
    }
    for (int i = t; i < Bb * Hh; i += 256) { g_hs[i] = 0.0f; g_cs[i] = 0.0f; }
    for (int i = t; i < Bb * 2 * Hh; i += 256) g_qstar[i] = 0.0f;
}

// ---------------- per-edge matvec + scatter: 8 threads/edge, vector red.global scatter ----
__global__ __launch_bounds__(256)
void k_msg(const int* __restrict__ src, const int* __restrict__ dst) {
    __shared__ float xs[32][Hh];
    __shared__ int   sid[32], did[32];
    int t = threadIdx.x;
    int e0 = blockIdx.x * 32;
    if (t < 32) { sid[t] = src[e0 + t]; did[t] = dst[e0 + t]; }
    __syncthreads();
#pragma unroll
    for (int p = 0; p < 8; p++) {
        int idx = p * 256 + t;
        int le2 = idx >> 6, c = idx & 63;
        xs[le2][c] = g_X[sid[le2] * Hh + c];
    }
    __syncthreads();

    int le = t >> 3;
    int c8 = (t & 7) * 8;
    const __half* we = g_we + (size_t)(e0 + le) * Hh * Hh + c8;
    float acc[8] = {};
#pragma unroll 16
    for (int i = 0; i < Hh; i++) {
        float xv = xs[le][i];
        uint4 raw = __ldcs((const uint4*)(we + i * Hh));
        const __half2* hp = (const __half2*)&raw;
#pragma unroll
        for (int j = 0; j < 4; j++) {
            float2 f = __half22float2(hp[j]);
            acc[2 * j]     = fmaf(xv, f.x, acc[2 * j]);
            acc[2 * j + 1] = fmaf(xv, f.y, acc[2 * j + 1]);
        }
    }
    float* ap = &g_agg[did[le] * Hh + c8];
    asm volatile("red.global.add.v4.f32 [%0], {%1, %2, %3, %4};"
                 :: "l"(ap), "f"(acc[0]), "f"(acc[1]), "f"(acc[2]), "f"(acc[3]) : "memory");
    asm volatile("red.global.add.v4.f32 [%0], {%1, %2, %3, %4};"
                 :: "l"(ap + 4), "f"(acc[4]), "f"(acc[5]), "f"(acc[6]), "f"(acc[7]) : "memory");
}

// ---------------- fused m = relu(agg/deg + X@root + cb) ; X = GRU(m, X) ----------------
__global__ void k_gru(const float* __restrict__ cr, const float* __restrict__ cb,
                      const float* __restrict__ wih, const float* __restrict__ whh,
                      const float* __restrict__ bih, const float* __restrict__ bhh) {
    __shared__ float xs[Hh], ms[Hh], gi[3 * Hh], gh[3 * Hh];
    int n = blockIdx.x, t = threadIdx.x;           // 192 threads
    if (t < Hh) xs[t] = g_X[n * Hh + t];
    __syncthreads();
    if (t < Hh) {
        float d = fmaxf(g_deg[n], 1.0f);
        float acc = g_agg[n * Hh + t] / d + cb[t];
        g_agg[n * Hh + t] = 0.0f;
#pragma unroll
        for (int i = 0; i < Hh; i++) acc = fmaf(xs[i], cr[i * Hh + t], acc);
        ms[t] = fmaxf(acc, 0.0f);
    }
    __syncthreads();
    {
        float a = bih[t], c = bhh[t];
#pragma unroll
        for (int i = 0; i < Hh; i++) {
            a = fmaf(ms[i], wih[i * 3 * Hh + t], a);
            c = fmaf(xs[i], whh[i * 3 * Hh + t], c);
        }
        gi[t] = a; gh[t] = c;
    }
    __syncthreads();
    if (t < Hh) {
        float r = sigf(gi[t] + gh[t]);
        float z = sigf(gi[Hh + t] + gh[Hh + t]);
        float ng = tanhf(gi[2 * Hh + t] + r * gh[2 * Hh + t]);
        g_X[n * Hh + t] = (1.0f - z) * ng + z * xs[t];
    }
}

// ---------------- Set2Set LSTM step ----------------
__global__ void k_lstm(const float* __restrict__ wih, const float* __restrict__ whh,
                       const float* __restrict__ bih, const float* __restrict__ bhh) {
    __shared__ float qs[2 * Hh], hr[Hh], g[4 * Hh];
    int b = blockIdx.x, t = threadIdx.x;           // 256 threads
    if (t < 2 * Hh) qs[t] = g_qstar[b * 2 * Hh + t];
    if (t < Hh) hr[t] = g_hs[b * Hh + t];
    __syncthreads();
    {
        float a = bih[t] + bhh[t];
#pragma unroll
        for (int i = 0; i < 2 * Hh; i++) a = fmaf(qs[i], wih[i * 4 * Hh + t], a);
#pragma unroll
        for (int i = 0; i < Hh; i++) a = fmaf(hr[i], whh[i * 4 * Hh + t], a);
        g[t] = a;
    }
    __syncthreads();
    if (t < Hh) {
        float ii = sigf(g[t]);
        float ff = sigf(g[Hh + t]);
        float gg = tanhf(g[2 * Hh + t]);
        float oo = sigf(g[3 * Hh + t]);
        float c2 = ff * g_cs[b * Hh + t] + ii * gg;
        float h2 = oo * tanhf(c2);
        g_cs[b * Hh + t] = c2;
        g_hs[b * Hh + t] = h2;
        g_qstar[b * 2 * Hh + t] = h2;
    }
}

// ---------------- en[n] = dot(X[n], hs[batch[n]]) ----------------
__global__ void k_en(const int* __restrict__ batch) {
    __shared__ float red[2];
    int n = blockIdx.x, o = threadIdx.x;           // 64 threads
    int b = batch[n];
    float v = g_X[n * Hh + o] * g_hs[b * Hh + o];
#pragma unroll
    for (int s = 16; s > 0; s >>= 1) v += __shfl_down_sync(0xffffffffu, v, s);
    if ((o & 31) == 0) red[o >> 5] = v;
    __syncthreads();
    if (o == 0) g_en[n] = red[0] + red[1];
}

// ---------------- per-graph softmax + weighted readout ----------------
__global__ __launch_bounds__(256)
void k_pool() {
    __shared__ float red[256];
    __shared__ float part[4][Hh];
    int b = blockIdx.x, t = threadIdx.x;           // 256 threads
    int s = g_ptr[b], e = g_ptr[b + 1];
    float m = -1e30f;
    for (int n = s + t; n < e; n += 256) m = fmaxf(m, g_en[n]);
    red[t] = m; __syncthreads();
    for (int st = 128; st > 0; st >>= 1) { if (t < st) red[t] = fmaxf(red[t], red[t + st]); __syncthreads(); }
    float mx = red[0]; __syncthreads();
    float ss = 0.0f;
    for (int n = s + t; n < e; n += 256) ss += expf(g_en[n] - mx);
    red[t] = ss; __syncthreads();
    for (int st = 128; st > 0; st >>= 1) { if (t < st) red[t] += red[t + st]; __syncthreads(); }
    float inv = 1.0f / (red[0] + 1e-16f);
    int ch = t >> 6, col = t & 63;
    float acc = 0.0f;
    for (int n = s + ch; n < e; n += 4) {
        float a = expf(g_en[n] - mx) * inv;
        acc = fmaf(a, g_X[n * Hh + col], acc);
    }
    part[ch][col] = acc; __syncthreads();
    if (t < Hh)
        g_qstar[b * 2 * Hh + Hh + t] = part[0][t] + part[1][t] + part[2][t] + part[3][t];
}

// ---------------- head ----------------
__global__ void k_final(const float* __restrict__ w1, const float* __restrict__ b1,
                        const float* __restrict__ w2, const float* __restrict__ b2,
                        float* __restrict__ out) {
    __shared__ float qs[2 * Hh], red[Hh];
    int b = blockIdx.x, t = threadIdx.x;           // 64 threads
    qs[t] = g_qstar[b * 2 * Hh + t];
    qs[Hh + t] = g_qstar[b * 2 * Hh + Hh + t];
    __syncthreads();
    float a = b1[t];
#pragma unroll
    for (int i = 0; i < 2 * Hh; i++) a = fmaf(qs[i], w1[i * Hh + t], a);
    a = fmaxf(a, 0.0f);
    red[t] = a * w2[t];
    __syncthreads();
    for (int st = 32; st > 0; st >>= 1) { if (t < st) red[t] += red[t + st]; __syncthreads(); }
    if (t == 0) out[b] = red[0] + b2[0];
}

// ---------------- launcher ----------------
extern "C" void kernel_launch(void* const* d_in, const int* in_sizes, int n_in,
                              void* d_out, int out_size) {
    const float* x         = (const float*)d_in[0];
    const int*   ei        = (const int*)d_in[1];
    const int*   batch     = (const int*)d_in[2];
    const float* edge_attr = (const float*)d_in[3];
    const float* lin0_w = (const float*)d_in[4];
    const float* lin0_b = (const float*)d_in[5];
    const float* nn_w1  = (const float*)d_in[6];
    const float* nn_b1  = (const float*)d_in[7];
    const float* nn_w2  = (const float*)d_in[8];
    const float* nn_b2  = (const float*)d_in[9];
    const float* conv_root = (const float*)d_in[10];
    const float* conv_bias = (const float*)d_in[11];
    const float* gru_wih = (const float*)d_in[12];
    const float* gru_whh = (const float*)d_in[13];
    const float* gru_bih = (const float*)d_in[14];
    const float* gru_bhh = (const float*)d_in[15];
    const float* lstm_wih = (const float*)d_in[16];
    const float* lstm_whh = (const float*)d_in[17];
    const float* lstm_bih = (const float*)d_in[18];
    const float* lstm_bhh = (const float*)d_in[19];
    const float* lin1_w = (const float*)d_in[20];
    const float* lin1_b = (const float*)d_in[21];
    const float* lin2_w = (const float*)d_in[22];
    const float* lin2_b = (const float*)d_in[23];

    const int* src = ei;
    const int* dst = ei + Ee;

    void *p_deg, *p_cnt;
    cudaGetSymbolAddress(&p_deg, g_deg);
    cudaGetSymbolAddress(&p_cnt, g_cnt);
    cudaMemsetAsync(p_deg, 0, Nn * sizeof(float), 0);
    cudaMemsetAsync(p_cnt, 0, Bb * sizeof(int), 0);

    // launch #4 (k_gemm_we) is the ncu-profiled one
    k_prep<<<512, 256>>>(nn_w2);                                     // 1
    k_lin0<<<Nn, Hh>>>(x, lin0_w, lin0_b);                           // 2
    k_mlp1<<<Ee, HID>>>(edge_attr, nn_w1, nn_b1);                    // 3
    k_gemm_we<<<dim3((Hh * Hh) / GBN, Ee / GBM), 256>>>(nn_b2);      // 4 <- profiled
    k_deg<<<(Ee + 255) / 256, 256>>>(dst);                           // 5
    k_cnt<<<(Nn + 255) / 256, 256>>>(batch);                         // 6
    k_scan<<<1, 256>>>();                                            // 7

    for (int it = 0; it < 3; it++) {
        k_msg<<<Ee / 32, 256>>>(src, dst);
        k_gru<<<Nn, 3 * Hh>>>(conv_root, conv_bias, gru_wih, gru_whh, gru_bih, gru_bhh);
    }

    for (int st = 0; st < 3; st++) {
        k_lstm<<<Bb, 4 * Hh>>>(lstm_wih, lstm_whh, lstm_bih, lstm_bhh);
        k_en<<<Nn, Hh>>>(batch);
        k_pool<<<Bb, 256>>>();
    }

    k_final<<<Bb, Hh>>>(lin1_w, lin1_b, lin2_w, lin2_b, (float*)d_out);
}

// round 14
// speedup vs baseline: 1.1850x; 1.0659x over previous
#include <cuda_runtime.h>
#include <cuda_fp16.h>
#include <mma.h>
#include <math.h>
#include <stdint.h>

using namespace nvcuda;

#define Nn  20000
#define Ee  80000
#define Hh  64
#define NFf 32
#define Bb  64
#define HID 128

// ---------------- device scratch (no allocations allowed) ----------------
__device__ float  g_X[Nn * Hh];
__device__ float  g_agg[Nn * Hh];              // zeroed at load; k_gru re-zeroes after use
__device__ __half g_hid[Ee * HID];             // edge MLP hidden (fp16)
__device__ __half g_w2h[HID * Hh * Hh];        // W2 in fp16 (1 MB)
__device__ __half g_we[(size_t)Ee * Hh * Hh];  // 655 MB edge weights (fp16)
__device__ float  g_deg[Nn];
__device__ int    g_cnt[Bb];
__device__ int    g_ptr[Bb + 1];
__device__ float  g_en[Nn];
__device__ float  g_hs[Bb * Hh];
__device__ float  g_cs[Bb * Hh];
__device__ float  g_qstar[Bb * 2 * Hh];

__device__ __forceinline__ float sigf(float x) { return 1.0f / (1.0f + expf(-x)); }

// ---------------- prep: W2 -> fp16 ----------------
__global__ void k_prep(const float* __restrict__ w2) {
    int i4 = (blockIdx.x * 256 + threadIdx.x) * 4;
    float4 v = *(const float4*)&w2[i4];
    *(__half2*)&g_w2h[i4]     = __floats2half2_rn(v.x, v.y);
    *(__half2*)&g_w2h[i4 + 2] = __floats2half2_rn(v.z, v.w);
}

// ---------------- lin0: X = relu(x @ W0 + b0) ----------------
__global__ void k_lin0(const float* __restrict__ x, const float* __restrict__ w,
                       const float* __restrict__ b) {
    __shared__ float xs[NFf];
    int n = blockIdx.x, o = threadIdx.x;           // 64 threads
    if (o < NFf) xs[o] = x[n * NFf + o];
    __syncthreads();
    float acc = b[o];
#pragma unroll
    for (int i = 0; i < NFf; i++) acc = fmaf(xs[i], w[i * Hh + o], acc);
    g_X[n * Hh + o] = fmaxf(acc, 0.0f);
}

// ---------------- edge MLP layer 1 (HMMA): hid = fp16(relu(ea @ W1 + b1)) ----------------
// Block: 64 edges x 128 outputs, K=64. ea/W1 converted fp16 on load. Bias preloaded in acc.
#define M1AST 72
#define M1BST 136
__global__ __launch_bounds__(256)
void k_mlp1(const float* __restrict__ ea, const float* __restrict__ w1,
            const float* __restrict__ b) {
    __shared__ __half As[64 * M1AST];       // ea tile, fp16
    __shared__ __half Bs[64 * M1BST];       // W1, fp16 [64 k][128 n]
    __shared__ float  bias_s[16 * 132];
    int t = threadIdx.x;                    // 256
    int e0 = blockIdx.x * 64;

    if (t < HID) {
        float bv = b[t];
#pragma unroll
        for (int r = 0; r < 16; r++) bias_s[r * 132 + t] = bv;
    }
    // A: 64 rows x 64 f32 -> fp16. Thread: row t>>2, cols (t&3)*16..+15
    {
        int lr = t >> 2, c16 = (t & 3) * 16;
        const float4* src = (const float4*)&ea[(size_t)(e0 + lr) * Hh + c16];
        __half hbuf[16];
#pragma unroll
        for (int q = 0; q < 4; q++) {
            float4 v = src[q];
            *(__half2*)&hbuf[q * 4]     = __floats2half2_rn(v.x, v.y);
            *(__half2*)&hbuf[q * 4 + 2] = __floats2half2_rn(v.z, v.w);
        }
        *(uint4*)&As[lr * M1AST + c16]     = *(uint4*)&hbuf[0];
        *(uint4*)&As[lr * M1AST + c16 + 8] = *(uint4*)&hbuf[8];
    }
    // B: W1 8192 f32 = 2048 float4; 8 per thread
#pragma unroll
    for (int p = 0; p < 8; p++) {
        int idx = p * 256 + t;
        int k = idx >> 5, n4 = (idx & 31) * 4;
        float4 v = ((const float4*)w1)[idx];
        __half2 h0 = __floats2half2_rn(v.x, v.y);
        __half2 h1 = __floats2half2_rn(v.z, v.w);
        *(__half2*)&Bs[k * M1BST + n4]     = h0;
        *(__half2*)&Bs[k * M1BST + n4 + 2] = h1;
    }
    __syncthreads();

    int wid = t >> 5, rt = wid & 3, ct = wid >> 2;   // 16-row tile, 64-col half
    wmma::fragment<wmma::accumulator, 16, 16, 16, float> c[4];
#pragma unroll
    for (int j = 0; j < 4; j++)
        wmma::load_matrix_sync(c[j], &bias_s[ct * 64 + j * 16], 132, wmma::mem_row_major);

#pragma unroll
    for (int k16 = 0; k16 < 4; k16++) {
        wmma::fragment<wmma::matrix_a, 16, 16, 16, __half, wmma::row_major> af;
        wmma::load_matrix_sync(af, &As[rt * 16 * M1AST + k16 * 16], M1AST);
#pragma unroll
        for (int j = 0; j < 4; j++) {
            wmma::fragment<wmma::matrix_b, 16, 16, 16, __half, wmma::row_major> bf;
            wmma::load_matrix_sync(bf, &Bs[k16 * 16 * M1BST + ct * 64 + j * 16], M1BST);
            wmma::mma_sync(c[j], af, bf, c[j]);
        }
    }

#pragma unroll
    for (int j = 0; j < 4; j++) {
        wmma::fragment<wmma::accumulator, 16, 16, 16, __half> h;
#pragma unroll
        for (int i = 0; i < c[j].num_elements; i++)
            h.x[i] = __float2half_rn(fmaxf(c[j].x[i], 0.0f));
        wmma::store_matrix_sync(&g_hid[(size_t)(e0 + rt * 16) * HID + ct * 64 + j * 16],
                                h, HID, wmma::mem_row_major);
    }
}

// ---------------- big GEMM (fp16 HMMA, round-8 exact form): we = fp16(hid @ W2 + b2) ----------
#define GBM 64
#define GBN 64
#define GBK 64
#define HSTR 72
#define BSTRc 68
__global__ __launch_bounds__(256)
void k_gemm_we(const float* __restrict__ bias) {
    __shared__ __half As[GBM * HSTR];
    __shared__ __half Bs[GBK * HSTR];
    __shared__ float  Cs[GBM * BSTRc];

    int bn = blockIdx.x;
    int bm = blockIdx.y;
    int t  = threadIdx.x;
    int wid = t >> 5;
    int rt = wid & 3;
    int ct = wid >> 2;

    wmma::fragment<wmma::accumulator, 16, 16, 16, float> c0, c1;
    wmma::fill_fragment(c0, 0.0f);
    wmma::fill_fragment(c1, 0.0f);

    const __half* A = g_hid + (size_t)bm * GBM * HID;
    const __half* Bg = g_w2h + bn * GBN;

    int lr = t >> 3;
    int lc = (t & 7) * 8;

    for (int kt = 0; kt < HID; kt += GBK) {
        *(float4*)&As[lr * HSTR + lc]        = *(const float4*)&A[lr * HID + kt + lc];
        *(float4*)&As[(lr + 32) * HSTR + lc] = *(const float4*)&A[(lr + 32) * HID + kt + lc];
        *(float4*)&Bs[lr * HSTR + lc]        = *(const float4*)&Bg[(size_t)(kt + lr) * (Hh * Hh) + lc];
        *(float4*)&Bs[(lr + 32) * HSTR + lc] = *(const float4*)&Bg[(size_t)(kt + lr + 32) * (Hh * Hh) + lc];
        __syncthreads();
#pragma unroll
        for (int k16 = 0; k16 < GBK / 16; k16++) {
            wmma::fragment<wmma::matrix_a, 16, 16, 16, __half, wmma::row_major> af;
            wmma::fragment<wmma::matrix_b, 16, 16, 16, __half, wmma::row_major> bf0, bf1;
            wmma::load_matrix_sync(af, &As[rt * 16 * HSTR + k16 * 16], HSTR);
            wmma::load_matrix_sync(bf0, &Bs[k16 * 16 * HSTR + ct * 32], HSTR);
            wmma::load_matrix_sync(bf1, &Bs[k16 * 16 * HSTR + ct * 32 + 16], HSTR);
            wmma::mma_sync(c0, af, bf0, c0);
            wmma::mma_sync(c1, af, bf1, c1);
        }
        __syncthreads();
    }

    wmma::store_matrix_sync(&Cs[rt * 16 * BSTRc + ct * 32], c0, BSTRc, wmma::mem_row_major);
    wmma::store_matrix_sync(&Cs[rt * 16 * BSTRc + ct * 32 + 16], c1, BSTRc, wmma::mem_row_major);
    __syncthreads();

    __half* C = g_we + (size_t)bm * GBM * (Hh * Hh) + bn * GBN;
#pragma unroll
    for (int p = 0; p < 4; p++) {
        int idx = p * 1024 + t * 4;
        int r = idx >> 6, c = idx & 63;
        float4 v = *(float4*)&Cs[r * BSTRc + c];
        int cg = bn * GBN + c;
        v.x += bias[cg + 0]; v.y += bias[cg + 1];
        v.z += bias[cg + 2]; v.w += bias[cg + 3];
        __half2 h0 = __floats2half2_rn(v.x, v.y);
        __half2 h1 = __floats2half2_rn(v.z, v.w);
        *(__half2*)&C[(size_t)r * (Hh * Hh) + c] = h0;
        *(__half2*)&C[(size_t)r * (Hh * Hh) + c + 2] = h1;
    }
}

// ---------------- degree / batch counts ----------------
__global__ void k_deg(const int* __restrict__ dst) {
    int e = blockIdx.x * blockDim.x + threadIdx.x;
    if (e < Ee) atomicAdd(&g_deg[dst[e]], 1.0f);
}
__global__ void k_cnt(const int* __restrict__ batch) {
    int n = blockIdx.x * blockDim.x + threadIdx.x;
    if (n < Nn) atomicAdd(&g_cnt[batch[n]], 1);
}
__global__ void k_scan() {
    int t = threadIdx.x;
    if (t == 0) {
        g_ptr[0] = 0;
        for (int b = 0; b < Bb; b++) g_ptr[b + 1] = g_ptr[b] + g_cnt[b];
    }
    for (int i = t; i < Bb * Hh; i += 256) { g_hs[i] = 0.0f; g_cs[i] = 0.0f; }
    for (int i = t; i < Bb * 2 * Hh; i += 256) g_qstar[i] = 0.0f;
}

// ---------------- per-edge matvec + scatter: 8 threads/edge, vector red.global scatter ----
__global__ __launch_bounds__(256)
void k_msg(const int* __restrict__ src, const int* __restrict__ dst) {
    __shared__ float xs[32][Hh];
    __shared__ int   sid[32], did[32];
    int t = threadIdx.x;
    int e0 = blockIdx.x * 32;
    if (t < 32) { sid[t] = src[e0 + t]; did[t] = dst[e0 + t]; }
    __syncthreads();
#pragma unroll
    for (int p = 0; p < 8; p++) {
        int idx = p * 256 + t;
        int le2 = idx >> 6, c = idx & 63;
        xs[le2][c] = g_X[sid[le2] * Hh + c];
    }
    __syncthreads();

    int le = t >> 3;
    int c8 = (t & 7) * 8;
    const __half* we = g_we + (size_t)(e0 + le) * Hh * Hh + c8;
    float acc[8] = {};
#pragma unroll 16
    for (int i = 0; i < Hh; i++) {
        float xv = xs[le][i];
        uint4 raw = __ldcs((const uint4*)(we + i * Hh));
        const __half2* hp = (const __half2*)&raw;
#pragma unroll
        for (int j = 0; j < 4; j++) {
            float2 f = __half22float2(hp[j]);
            acc[2 * j]     = fmaf(xv, f.x, acc[2 * j]);
            acc[2 * j + 1] = fmaf(xv, f.y, acc[2 * j + 1]);
        }
    }
    float* ap = &g_agg[did[le] * Hh + c8];
    asm volatile("red.global.add.v4.f32 [%0], {%1, %2, %3, %4};"
                 :: "l"(ap), "f"(acc[0]), "f"(acc[1]), "f"(acc[2]), "f"(acc[3]) : "memory");
    asm volatile("red.global.add.v4.f32 [%0], {%1, %2, %3, %4};"
                 :: "l"(ap + 4), "f"(acc[4]), "f"(acc[5]), "f"(acc[6]), "f"(acc[7]) : "memory");
}

// ---------------- fused m = relu(agg/deg + X@root + cb) ; X = GRU(m, X) ----------------
__global__ void k_gru(const float* __restrict__ cr, const float* __restrict__ cb,
                      const float* __restrict__ wih, const float* __restrict__ whh,
                      const float* __restrict__ bih, const float* __restrict__ bhh) {
    __shared__ float xs[Hh], ms[Hh], gi[3 * Hh], gh[3 * Hh];
    int n = blockIdx.x, t = threadIdx.x;           // 192 threads
    if (t < Hh) xs[t] = g_X[n * Hh + t];
    __syncthreads();
    if (t < Hh) {
        float d = fmaxf(g_deg[n], 1.0f);
        float acc = g_agg[n * Hh + t] / d + cb[t];
        g_agg[n * Hh + t] = 0.0f;
#pragma unroll
        for (int i = 0; i < Hh; i++) acc = fmaf(xs[i], cr[i * Hh + t], acc);
        ms[t] = fmaxf(acc, 0.0f);
    }
    __syncthreads();
    {
        float a = bih[t], c = bhh[t];
#pragma unroll
        for (int i = 0; i < Hh; i++) {
            a = fmaf(ms[i], wih[i * 3 * Hh + t], a);
            c = fmaf(xs[i], whh[i * 3 * Hh + t], c);
        }
        gi[t] = a; gh[t] = c;
    }
    __syncthreads();
    if (t < Hh) {
        float r = sigf(gi[t] + gh[t]);
        float z = sigf(gi[Hh + t] + gh[Hh + t]);
        float ng = tanhf(gi[2 * Hh + t] + r * gh[2 * Hh + t]);
        g_X[n * Hh + t] = (1.0f - z) * ng + z * xs[t];
    }
}

// ---------------- Set2Set LSTM step ----------------
__global__ void k_lstm(const float* __restrict__ wih, const float* __restrict__ whh,
                       const float* __restrict__ bih, const float* __restrict__ bhh) {
    __shared__ float qs[2 * Hh], hr[Hh], g[4 * Hh];
    int b = blockIdx.x, t = threadIdx.x;           // 256 threads
    if (t < 2 * Hh) qs[t] = g_qstar[b * 2 * Hh + t];
    if (t < Hh) hr[t] = g_hs[b * Hh + t];
    __syncthreads();
    {
        float a = bih[t] + bhh[t];
#pragma unroll
        for (int i = 0; i < 2 * Hh; i++) a = fmaf(qs[i], wih[i * 4 * Hh + t], a);
#pragma unroll
        for (int i = 0; i < Hh; i++) a = fmaf(hr[i], whh[i * 4 * Hh + t], a);
        g[t] = a;
    }
    __syncthreads();
    if (t < Hh) {
        float ii = sigf(g[t]);
        float ff = sigf(g[Hh + t]);
        float gg = tanhf(g[2 * Hh + t]);
        float oo = sigf(g[3 * Hh + t]);
        float c2 = ff * g_cs[b * Hh + t] + ii * gg;
        float h2 = oo * tanhf(c2);
        g_cs[b * Hh + t] = c2;
        g_hs[b * Hh + t] = h2;
        g_qstar[b * 2 * Hh + t] = h2;
    }
}

// ---------------- en[n] = dot(X[n], hs[batch[n]]) ----------------
__global__ void k_en(const int* __restrict__ batch) {
    __shared__ float red[2];
    int n = blockIdx.x, o = threadIdx.x;           // 64 threads
    int b = batch[n];
    float v = g_X[n * Hh + o] * g_hs[b * Hh + o];
#pragma unroll
    for (int s = 16; s > 0; s >>= 1) v += __shfl_down_sync(0xffffffffu, v, s);
    if ((o & 31) == 0) red[o >> 5] = v;
    __syncthreads();
    if (o == 0) g_en[n] = red[0] + red[1];
}

// ---------------- per-graph softmax + weighted readout ----------------
__global__ __launch_bounds__(256)
void k_pool() {
    __shared__ float red[256];
    __shared__ float part[4][Hh];
    int b = blockIdx.x, t = threadIdx.x;           // 256 threads
    int s = g_ptr[b], e = g_ptr[b + 1];
    float m = -1e30f;
    for (int n = s + t; n < e; n += 256) m = fmaxf(m, g_en[n]);
    red[t] = m; __syncthreads();
    for (int st = 128; st > 0; st >>= 1) { if (t < st) red[t] = fmaxf(red[t], red[t + st]); __syncthreads(); }
    float mx = red[0]; __syncthreads();
    float ss = 0.0f;
    for (int n = s + t; n < e; n += 256) ss += expf(g_en[n] - mx);
    red[t] = ss; __syncthreads();
    for (int st = 128; st > 0; st >>= 1) { if (t < st) red[t] += red[t + st]; __syncthreads(); }
    float inv = 1.0f / (red[0] + 1e-16f);
    int ch = t >> 6, col = t & 63;
    float acc = 0.0f;
    for (int n = s + ch; n < e; n += 4) {
        float a = expf(g_en[n] - mx) * inv;
        acc = fmaf(a, g_X[n * Hh + col], acc);
    }
    part[ch][col] = acc; __syncthreads();
    if (t < Hh)
        g_qstar[b * 2 * Hh + Hh + t] = part[0][t] + part[1][t] + part[2][t] + part[3][t];
}

// ---------------- head ----------------
__global__ void k_final(const float* __restrict__ w1, const float* __restrict__ b1,
                        const float* __restrict__ w2, const float* __restrict__ b2,
                        float* __restrict__ out) {
    __shared__ float qs[2 * Hh], red[Hh];
    int b = blockIdx.x, t = threadIdx.x;           // 64 threads
    qs[t] = g_qstar[b * 2 * Hh + t];
    qs[Hh + t] = g_qstar[b * 2 * Hh + Hh + t];
    __syncthreads();
    float a = b1[t];
#pragma unroll
    for (int i = 0; i < 2 * Hh; i++) a = fmaf(qs[i], w1[i * Hh + t], a);
    a = fmaxf(a, 0.0f);
    red[t] = a * w2[t];
    __syncthreads();
    for (int st = 32; st > 0; st >>= 1) { if (t < st) red[t] += red[t + st]; __syncthreads(); }
    if (t == 0) out[b] = red[0] + b2[0];
}

// ---------------- launcher ----------------
extern "C" void kernel_launch(void* const* d_in, const int* in_sizes, int n_in,
                              void* d_out, int out_size) {
    const float* x         = (const float*)d_in[0];
    const int*   ei        = (const int*)d_in[1];
    const int*   batch     = (const int*)d_in[2];
    const float* edge_attr = (const float*)d_in[3];
    const float* lin0_w = (const float*)d_in[4];
    const float* lin0_b = (const float*)d_in[5];
    const float* nn_w1  = (const float*)d_in[6];
    const float* nn_b1  = (const float*)d_in[7];
    const float* nn_w2  = (const float*)d_in[8];
    const float* nn_b2  = (const float*)d_in[9];
    const float* conv_root = (const float*)d_in[10];
    const float* conv_bias = (const float*)d_in[11];
    const float* gru_wih = (const float*)d_in[12];
    const float* gru_whh = (const float*)d_in[13];
    const float* gru_bih = (const float*)d_in[14];
    const float* gru_bhh = (const float*)d_in[15];
    const float* lstm_wih = (const float*)d_in[16];
    const float* lstm_whh = (const float*)d_in[17];
    const float* lstm_bih = (const float*)d_in[18];
    const float* lstm_bhh = (const float*)d_in[19];
    const float* lin1_w = (const float*)d_in[20];
    const float* lin1_b = (const float*)d_in[21];
    const float* lin2_w = (const float*)d_in[22];
    const float* lin2_b = (const float*)d_in[23];

    const int* src = ei;
    const int* dst = ei + Ee;

    void *p_deg, *p_cnt;
    cudaGetSymbolAddress(&p_deg, g_deg);
    cudaGetSymbolAddress(&p_cnt, g_cnt);
    cudaMemsetAsync(p_deg, 0, Nn * sizeof(float), 0);
    cudaMemsetAsync(p_cnt, 0, Bb * sizeof(int), 0);

    // launch #4 (k_gemm_we) is the ncu-profiled one
    k_prep<<<512, 256>>>(nn_w2);                                     // 1
    k_lin0<<<Nn, Hh>>>(x, lin0_w, lin0_b);                           // 2
    k_mlp1<<<Ee / 64, 256>>>(edge_attr, nn_w1, nn_b1);               // 3
    k_gemm_we<<<dim3((Hh * Hh) / GBN, Ee / GBM), 256>>>(nn_b2);      // 4 <- profiled
    k_deg<<<(Ee + 255) / 256, 256>>>(dst);                           // 5
    k_cnt<<<(Nn + 255) / 256, 256>>>(batch);                         // 6
    k_scan<<<1, 256>>>();                                            // 7

    for (int it = 0; it < 3; it++) {
        k_msg<<<Ee / 32, 256>>>(src, dst);
        k_gru<<<Nn, 3 * Hh>>>(conv_root, conv_bias, gru_wih, gru_whh, gru_bih, gru_bhh);
    }

    for (int st = 0; st < 3; st++) {
        k_lstm<<<Bb, 4 * Hh>>>(lstm_wih, lstm_whh, lstm_bih, lstm_bhh);
        k_en<<<Nn, Hh>>>(batch);
        k_pool<<<Bb, 256>>>();
    }

    k_final<<<Bb, Hh>>>(lin1_w, lin1_b, lin2_w, lin2_b, (float*)d_out);
}

// round 15
// speedup vs baseline: 1.2539x; 1.0581x over previous
#include <cuda_runtime.h>
#include <cuda_fp16.h>
#include <mma.h>
#include <math.h>
#include <stdint.h>

using namespace nvcuda;

#define Nn  20000
#define Ee  80000
#define Hh  64
#define NFf 32
#define Bb  64
#define HID 128

// ---------------- device scratch (no allocations allowed) ----------------
__device__ float  g_X[Nn * Hh];
__device__ float  g_agg[Nn * Hh];              // zeroed at load; k_gru re-zeroes after use
__device__ __half g_hid[Ee * HID];             // edge MLP hidden (fp16)
__device__ __half g_w2h[HID * Hh * Hh];        // W2 in fp16 (1 MB)
__device__ __half g_we[(size_t)Ee * Hh * Hh];  // 655 MB edge weights (fp16)
__device__ float  g_deg[Nn];
__device__ int    g_cnt[Bb];
__device__ int    g_ptr[Bb + 1];
__device__ float  g_en[Nn];
__device__ float  g_hs[Bb * Hh];
__device__ float  g_cs[Bb * Hh];
__device__ float  g_qstar[Bb * 2 * Hh];

__device__ __forceinline__ float sigf(float x) { return 1.0f / (1.0f + expf(-x)); }

// ---------------- prep: W2 -> fp16 ----------------
__global__ void k_prep(const float* __restrict__ w2) {
    int i4 = (blockIdx.x * 256 + threadIdx.x) * 4;
    float4 v = *(const float4*)&w2[i4];
    *(__half2*)&g_w2h[i4]     = __floats2half2_rn(v.x, v.y);
    *(__half2*)&g_w2h[i4 + 2] = __floats2half2_rn(v.z, v.w);
}

// ---------------- lin0: X = relu(x @ W0 + b0) ----------------
__global__ void k_lin0(const float* __restrict__ x, const float* __restrict__ w,
                       const float* __restrict__ b) {
    __shared__ float xs[NFf];
    int n = blockIdx.x, o = threadIdx.x;           // 64 threads
    if (o < NFf) xs[o] = x[n * NFf + o];
    __syncthreads();
    float acc = b[o];
#pragma unroll
    for (int i = 0; i < NFf; i++) acc = fmaf(xs[i], w[i * Hh + o], acc);
    g_X[n * Hh + o] = fmaxf(acc, 0.0f);
}

// ---------------- edge MLP layer 1 (HMMA): hid = fp16(relu(ea @ W1 + b1)) ----------------
#define M1AST 72
#define M1BST 136
__global__ __launch_bounds__(256)
void k_mlp1(const float* __restrict__ ea, const float* __restrict__ w1,
            const float* __restrict__ b) {
    __shared__ __half As[64 * M1AST];       // ea tile, fp16
    __shared__ __half Bs[64 * M1BST];       // W1, fp16 [64 k][128 n]
    __shared__ float  bias_s[16 * 132];
    int t = threadIdx.x;                    // 256
    int e0 = blockIdx.x * 64;

    if (t < HID) {
        float bv = b[t];
#pragma unroll
        for (int r = 0; r < 16; r++) bias_s[r * 132 + t] = bv;
    }
    {
        int lr = t >> 2, c16 = (t & 3) * 16;
        const float4* src = (const float4*)&ea[(size_t)(e0 + lr) * Hh + c16];
        __half hbuf[16];
#pragma unroll
        for (int q = 0; q < 4; q++) {
            float4 v = src[q];
            *(__half2*)&hbuf[q * 4]     = __floats2half2_rn(v.x, v.y);
            *(__half2*)&hbuf[q * 4 + 2] = __floats2half2_rn(v.z, v.w);
        }
        *(uint4*)&As[lr * M1AST + c16]     = *(uint4*)&hbuf[0];
        *(uint4*)&As[lr * M1AST + c16 + 8] = *(uint4*)&hbuf[8];
    }
#pragma unroll
    for (int p = 0; p < 8; p++) {
        int idx = p * 256 + t;
        int k = idx >> 5, n4 = (idx & 31) * 4;
        float4 v = ((const float4*)w1)[idx];
        __half2 h0 = __floats2half2_rn(v.x, v.y);
        __half2 h1 = __floats2half2_rn(v.z, v.w);
        *(__half2*)&Bs[k * M1BST + n4]     = h0;
        *(__half2*)&Bs[k * M1BST + n4 + 2] = h1;
    }
    __syncthreads();

    int wid = t >> 5, rt = wid & 3, ct = wid >> 2;
    wmma::fragment<wmma::accumulator, 16, 16, 16, float> c[4];
#pragma unroll
    for (int j = 0; j < 4; j++)
        wmma::load_matrix_sync(c[j], &bias_s[ct * 64 + j * 16], 132, wmma::mem_row_major);

#pragma unroll
    for (int k16 = 0; k16 < 4; k16++) {
        wmma::fragment<wmma::matrix_a, 16, 16, 16, __half, wmma::row_major> af;
        wmma::load_matrix_sync(af, &As[rt * 16 * M1AST + k16 * 16], M1AST);
#pragma unroll
        for (int j = 0; j < 4; j++) {
            wmma::fragment<wmma::matrix_b, 16, 16, 16, __half, wmma::row_major> bf;
            wmma::load_matrix_sync(bf, &Bs[k16 * 16 * M1BST + ct * 64 + j * 16], M1BST);
            wmma::mma_sync(c[j], af, bf, c[j]);
        }
    }

#pragma unroll
    for (int j = 0; j < 4; j++) {
        wmma::fragment<wmma::accumulator, 16, 16, 16, __half> h;
#pragma unroll
        for (int i = 0; i < c[j].num_elements; i++)
            h.x[i] = __float2half_rn(fmaxf(c[j].x[i], 0.0f));
        wmma::store_matrix_sync(&g_hid[(size_t)(e0 + rt * 16) * HID + ct * 64 + j * 16],
                                h, HID, wmma::mem_row_major);
    }
}

// ---------------- big GEMM (fp16 HMMA, round-8 exact form): we = fp16(hid @ W2 + b2) ----------
#define GBM 64
#define GBN 64
#define GBK 64
#define HSTR 72
#define BSTRc 68
__global__ __launch_bounds__(256)
void k_gemm_we(const float* __restrict__ bias) {
    __shared__ __half As[GBM * HSTR];
    __shared__ __half Bs[GBK * HSTR];
    __shared__ float  Cs[GBM * BSTRc];

    int bn = blockIdx.x;
    int bm = blockIdx.y;
    int t  = threadIdx.x;
    int wid = t >> 5;
    int rt = wid & 3;
    int ct = wid >> 2;

    wmma::fragment<wmma::accumulator, 16, 16, 16, float> c0, c1;
    wmma::fill_fragment(c0, 0.0f);
    wmma::fill_fragment(c1, 0.0f);

    const __half* A = g_hid + (size_t)bm * GBM * HID;
    const __half* Bg = g_w2h + bn * GBN;

    int lr = t >> 3;
    int lc = (t & 7) * 8;

    for (int kt = 0; kt < HID; kt += GBK) {
        *(float4*)&As[lr * HSTR + lc]        = *(const float4*)&A[lr * HID + kt + lc];
        *(float4*)&As[(lr + 32) * HSTR + lc] = *(const float4*)&A[(lr + 32) * HID + kt + lc];
        *(float4*)&Bs[lr * HSTR + lc]        = *(const float4*)&Bg[(size_t)(kt + lr) * (Hh * Hh) + lc];
        *(float4*)&Bs[(lr + 32) * HSTR + lc] = *(const float4*)&Bg[(size_t)(kt + lr + 32) * (Hh * Hh) + lc];
        __syncthreads();
#pragma unroll
        for (int k16 = 0; k16 < GBK / 16; k16++) {
            wmma::fragment<wmma::matrix_a, 16, 16, 16, __half, wmma::row_major> af;
            wmma::fragment<wmma::matrix_b, 16, 16, 16, __half, wmma::row_major> bf0, bf1;
            wmma::load_matrix_sync(af, &As[rt * 16 * HSTR + k16 * 16], HSTR);
            wmma::load_matrix_sync(bf0, &Bs[k16 * 16 * HSTR + ct * 32], HSTR);
            wmma::load_matrix_sync(bf1, &Bs[k16 * 16 * HSTR + ct * 32 + 16], HSTR);
            wmma::mma_sync(c0, af, bf0, c0);
            wmma::mma_sync(c1, af, bf1, c1);
        }
        __syncthreads();
    }

    wmma::store_matrix_sync(&Cs[rt * 16 * BSTRc + ct * 32], c0, BSTRc, wmma::mem_row_major);
    wmma::store_matrix_sync(&Cs[rt * 16 * BSTRc + ct * 32 + 16], c1, BSTRc, wmma::mem_row_major);
    __syncthreads();

    __half* C = g_we + (size_t)bm * GBM * (Hh * Hh) + bn * GBN;
#pragma unroll
    for (int p = 0; p < 4; p++) {
        int idx = p * 1024 + t * 4;
        int r = idx >> 6, c = idx & 63;
        float4 v = *(float4*)&Cs[r * BSTRc + c];
        int cg = bn * GBN + c;
        v.x += bias[cg + 0]; v.y += bias[cg + 1];
        v.z += bias[cg + 2]; v.w += bias[cg + 3];
        __half2 h0 = __floats2half2_rn(v.x, v.y);
        __half2 h1 = __floats2half2_rn(v.z, v.w);
        *(__half2*)&C[(size_t)r * (Hh * Hh) + c] = h0;
        *(__half2*)&C[(size_t)r * (Hh * Hh) + c + 2] = h1;
    }
}

// ---------------- degree / batch counts ----------------
__global__ void k_deg(const int* __restrict__ dst) {
    int e = blockIdx.x * blockDim.x + threadIdx.x;
    if (e < Ee) atomicAdd(&g_deg[dst[e]], 1.0f);
}
__global__ void k_cnt(const int* __restrict__ batch) {
    int n = blockIdx.x * blockDim.x + threadIdx.x;
    if (n < Nn) atomicAdd(&g_cnt[batch[n]], 1);
}
__global__ void k_scan() {
    int t = threadIdx.x;
    if (t == 0) {
        g_ptr[0] = 0;
        for (int b = 0; b < Bb; b++) g_ptr[b + 1] = g_ptr[b] + g_cnt[b];
    }
    for (int i = t; i < Bb * Hh; i += 256) { g_hs[i] = 0.0f; g_cs[i] = 0.0f; }
    for (int i = t; i < Bb * 2 * Hh; i += 256) g_qstar[i] = 0.0f;
}

// ---------------- per-edge matvec + scatter: 8 threads/edge, vector red.global scatter ----
__global__ __launch_bounds__(256)
void k_msg(const int* __restrict__ src, const int* __restrict__ dst) {
    __shared__ float xs[32][Hh];
    __shared__ int   sid[32], did[32];
    int t = threadIdx.x;
    int e0 = blockIdx.x * 32;
    if (t < 32) { sid[t] = src[e0 + t]; did[t] = dst[e0 + t]; }
    __syncthreads();
#pragma unroll
    for (int p = 0; p < 8; p++) {
        int idx = p * 256 + t;
        int le2 = idx >> 6, c = idx & 63;
        xs[le2][c] = g_X[sid[le2] * Hh + c];
    }
    __syncthreads();

    int le = t >> 3;
    int c8 = (t & 7) * 8;
    const __half* we = g_we + (size_t)(e0 + le) * Hh * Hh + c8;
    float acc[8] = {};
#pragma unroll 16
    for (int i = 0; i < Hh; i++) {
        float xv = xs[le][i];
        uint4 raw = __ldcs((const uint4*)(we + i * Hh));
        const __half2* hp = (const __half2*)&raw;
#pragma unroll
        for (int j = 0; j < 4; j++) {
            float2 f = __half22float2(hp[j]);
            acc[2 * j]     = fmaf(xv, f.x, acc[2 * j]);
            acc[2 * j + 1] = fmaf(xv, f.y, acc[2 * j + 1]);
        }
    }
    float* ap = &g_agg[did[le] * Hh + c8];
    asm volatile("red.global.add.v4.f32 [%0], {%1, %2, %3, %4};"
                 :: "l"(ap), "f"(acc[0]), "f"(acc[1]), "f"(acc[2]), "f"(acc[3]) : "memory");
    asm volatile("red.global.add.v4.f32 [%0], {%1, %2, %3, %4};"
                 :: "l"(ap + 4), "f"(acc[4]), "f"(acc[5]), "f"(acc[6]), "f"(acc[7]) : "memory");
}

// ---------------- fused GRU: 4 nodes per block (weight loads amortized 4x) ----------------
__global__ __launch_bounds__(192)
void k_gru(const float* __restrict__ cr, const float* __restrict__ cb,
           const float* __restrict__ wih, const float* __restrict__ whh,
           const float* __restrict__ bih, const float* __restrict__ bhh) {
    __shared__ float xs[4][Hh], ms[4][Hh];
    __shared__ float gi[4][3 * Hh], gh[4][3 * Hh];
    int n0 = blockIdx.x * 4;
    int t = threadIdx.x;                           // 192 threads
    for (int idx = t; idx < 4 * Hh; idx += 192)
        xs[idx >> 6][idx & 63] = g_X[(n0 + (idx >> 6)) * Hh + (idx & 63)];
    __syncthreads();
    if (t < Hh) {
        float acc[4];
#pragma unroll
        for (int q = 0; q < 4; q++) {
            float d = fmaxf(g_deg[n0 + q], 1.0f);
            acc[q] = g_agg[(n0 + q) * Hh + t] / d + cb[t];
            g_agg[(n0 + q) * Hh + t] = 0.0f;
        }
#pragma unroll
        for (int i = 0; i < Hh; i++) {
            float w = cr[i * Hh + t];
#pragma unroll
            for (int q = 0; q < 4; q++) acc[q] = fmaf(xs[q][i], w, acc[q]);
        }
#pragma unroll
        for (int q = 0; q < 4; q++) ms[q][t] = fmaxf(acc[q], 0.0f);
    }
    __syncthreads();
    {
        float bi = bih[t], bh = bhh[t];
        float a[4], c[4];
#pragma unroll
        for (int q = 0; q < 4; q++) { a[q] = bi; c[q] = bh; }
#pragma unroll
        for (int i = 0; i < Hh; i++) {
            float wa = wih[i * 3 * Hh + t];
            float wb = whh[i * 3 * Hh + t];
#pragma unroll
            for (int q = 0; q < 4; q++) {
                a[q] = fmaf(ms[q][i], wa, a[q]);
                c[q] = fmaf(xs[q][i], wb, c[q]);
            }
        }
#pragma unroll
        for (int q = 0; q < 4; q++) { gi[q][t] = a[q]; gh[q][t] = c[q]; }
    }
    __syncthreads();
    if (t < Hh) {
#pragma unroll
        for (int q = 0; q < 4; q++) {
            float r = sigf(gi[q][t] + gh[q][t]);
            float z = sigf(gi[q][Hh + t] + gh[q][Hh + t]);
            float ng = tanhf(gi[q][2 * Hh + t] + r * gh[q][2 * Hh + t]);
            g_X[(n0 + q) * Hh + t] = (1.0f - z) * ng + z * xs[q][t];
        }
    }
}

// ---------------- Set2Set LSTM step ----------------
__global__ void k_lstm(const float* __restrict__ wih, const float* __restrict__ whh,
                       const float* __restrict__ bih, const float* __restrict__ bhh) {
    __shared__ float qs[2 * Hh], hr[Hh], g[4 * Hh];
    int b = blockIdx.x, t = threadIdx.x;           // 256 threads
    if (t < 2 * Hh) qs[t] = g_qstar[b * 2 * Hh + t];
    if (t < Hh) hr[t] = g_hs[b * Hh + t];
    __syncthreads();
    {
        float a = bih[t] + bhh[t];
#pragma unroll
        for (int i = 0; i < 2 * Hh; i++) a = fmaf(qs[i], wih[i * 4 * Hh + t], a);
#pragma unroll
        for (int i = 0; i < Hh; i++) a = fmaf(hr[i], whh[i * 4 * Hh + t], a);
        g[t] = a;
    }
    __syncthreads();
    if (t < Hh) {
        float ii = sigf(g[t]);
        float ff = sigf(g[Hh + t]);
        float gg = tanhf(g[2 * Hh + t]);
        float oo = sigf(g[3 * Hh + t]);
        float c2 = ff * g_cs[b * Hh + t] + ii * gg;
        float h2 = oo * tanhf(c2);
        g_cs[b * Hh + t] = c2;
        g_hs[b * Hh + t] = h2;
        g_qstar[b * 2 * Hh + t] = h2;
    }
}

// ---------------- en[n] = dot(X[n], hs[batch[n]]) ----------------
__global__ void k_en(const int* __restrict__ batch) {
    __shared__ float red[2];
    int n = blockIdx.x, o = threadIdx.x;           // 64 threads
    int b = batch[n];
    float v = g_X[n * Hh + o] * g_hs[b * Hh + o];
#pragma unroll
    for (int s = 16; s > 0; s >>= 1) v += __shfl_down_sync(0xffffffffu, v, s);
    if ((o & 31) == 0) red[o >> 5] = v;
    __syncthreads();
    if (o == 0) g_en[n] = red[0] + red[1];
}

// ---------------- per-graph softmax + weighted readout ----------------
__global__ __launch_bounds__(256)
void k_pool() {
    __shared__ float red[256];
    __shared__ float part[4][Hh];
    int b = blockIdx.x, t = threadIdx.x;           // 256 threads
    int s = g_ptr[b], e = g_ptr[b + 1];
    float m = -1e30f;
    for (int n = s + t; n < e; n += 256) m = fmaxf(m, g_en[n]);
    red[t] = m; __syncthreads();
    for (int st = 128; st > 0; st >>= 1) { if (t < st) red[t] = fmaxf(red[t], red[t + st]); __syncthreads(); }
    float mx = red[0]; __syncthreads();
    float ss = 0.0f;
    for (int n = s + t; n < e; n += 256) ss += expf(g_en[n] - mx);
    red[t] = ss; __syncthreads();
    for (int st = 128; st > 0; st >>= 1) { if (t < st) red[t] += red[t + st]; __syncthreads(); }
    float inv = 1.0f / (red[0] + 1e-16f);
    int ch = t >> 6, col = t & 63;
    float acc = 0.0f;
    for (int n = s + ch; n < e; n += 4) {
        float a = expf(g_en[n] - mx) * inv;
        acc = fmaf(a, g_X[n * Hh + col], acc);
    }
    part[ch][col] = acc; __syncthreads();
    if (t < Hh)
        g_qstar[b * 2 * Hh + Hh + t] = part[0][t] + part[1][t] + part[2][t] + part[3][t];
}

// ---------------- head ----------------
__global__ void k_final(const float* __restrict__ w1, const float* __restrict__ b1,
                        const float* __restrict__ w2, const float* __restrict__ b2,
                        float* __restrict__ out) {
    __shared__ float qs[2 * Hh], red[Hh];
    int b = blockIdx.x, t = threadIdx.x;           // 64 threads
    qs[t] = g_qstar[b * 2 * Hh + t];
    qs[Hh + t] = g_qstar[b * 2 * Hh + Hh + t];
    __syncthreads();
    float a = b1[t];
#pragma unroll
    for (int i = 0; i < 2 * Hh; i++) a = fmaf(qs[i], w1[i * Hh + t], a);
    a = fmaxf(a, 0.0f);
    red[t] = a * w2[t];
    __syncthreads();
    for (int st = 32; st > 0; st >>= 1) { if (t < st) red[t] += red[t + st]; __syncthreads(); }
    if (t == 0) out[b] = red[0] + b2[0];
}

// ---------------- launcher ----------------
extern "C" void kernel_launch(void* const* d_in, const int* in_sizes, int n_in,
                              void* d_out, int out_size) {
    const float* x         = (const float*)d_in[0];
    const int*   ei        = (const int*)d_in[1];
    const int*   batch     = (const int*)d_in[2];
    const float* edge_attr = (const float*)d_in[3];
    const float* lin0_w = (const float*)d_in[4];
    const float* lin0_b = (const float*)d_in[5];
    const float* nn_w1  = (const float*)d_in[6];
    const float* nn_b1  = (const float*)d_in[7];
    const float* nn_w2  = (const float*)d_in[8];
    const float* nn_b2  = (const float*)d_in[9];
    const float* conv_root = (const float*)d_in[10];
    const float* conv_bias = (const float*)d_in[11];
    const float* gru_wih = (const float*)d_in[12];
    const float* gru_whh = (const float*)d_in[13];
    const float* gru_bih = (const float*)d_in[14];
    const float* gru_bhh = (const float*)d_in[15];
    const float* lstm_wih = (const float*)d_in[16];
    const float* lstm_whh = (const float*)d_in[17];
    const float* lstm_bih = (const float*)d_in[18];
    const float* lstm_bhh = (const float*)d_in[19];
    const float* lin1_w = (const float*)d_in[20];
    const float* lin1_b = (const float*)d_in[21];
    const float* lin2_w = (const float*)d_in[22];
    const float* lin2_b = (const float*)d_in[23];

    const int* src = ei;
    const int* dst = ei + Ee;

    void *p_deg, *p_cnt;
    cudaGetSymbolAddress(&p_deg, g_deg);
    cudaGetSymbolAddress(&p_cnt, g_cnt);
    cudaMemsetAsync(p_deg, 0, Nn * sizeof(float), 0);
    cudaMemsetAsync(p_cnt, 0, Bb * sizeof(int), 0);

    // launch #4 (k_gemm_we) is the ncu-profiled one
    k_prep<<<512, 256>>>(nn_w2);                                     // 1
    k_lin0<<<Nn, Hh>>>(x, lin0_w, lin0_b);                           // 2
    k_mlp1<<<Ee / 64, 256>>>(edge_attr, nn_w1, nn_b1);               // 3
    k_gemm_we<<<dim3((Hh * Hh) / GBN, Ee / GBM), 256>>>(nn_b2);      // 4 <- profiled
    k_deg<<<(Ee + 255) / 256, 256>>>(dst);                           // 5
    k_cnt<<<(Nn + 255) / 256, 256>>>(batch);                         // 6
    k_scan<<<1, 256>>>();                                            // 7

    for (int it = 0; it < 3; it++) {
        k_msg<<<Ee / 32, 256>>>(src, dst);
        k_gru<<<Nn / 4, 192>>>(conv_root, conv_bias, gru_wih, gru_whh, gru_bih, gru_bhh);
    }

    for (int st = 0; st < 3; st++) {
        k_lstm<<<Bb, 4 * Hh>>>(lstm_wih, lstm_whh, lstm_bih, lstm_bhh);
        k_en<<<Nn, Hh>>>(batch);
        k_pool<<<Bb, 256>>>();
    }

    k_final<<<Bb, Hh>>>(lin1_w, lin1_b, lin2_w, lin2_b, (float*)d_out);
}